// round 9
// baseline (speedup 1.0000x reference)
#include <cuda_runtime.h>
#include <cuda_fp16.h>
#include <cstdint>

#define BATCH 1048576
#define HID 64

// ---------------- device-global scratch ----------------
// t_j stored in PERMUTED word layout (fragment-native, see midk A-loads)
__device__ __half g_t[(size_t)5 * BATCH * HID];
__device__ float  g_sums[6][2][64];
__device__ float  g_aff [6][2][64];
__device__ uint4  g_Bfrag[4 * 4 * 8 * 32];   // [j][k4][n8][lane] hi(x,y)/lo(z,w)
__device__ uint4  g_OBfrag[5 * 4 * 32];      // [j][k4][lane] out-tile frags (N=8, cols 0..2 real)
__device__ float  g_cbias[64];
__device__ float  g_bout2[3];
__device__ float  g_pout[(size_t)3 * BATCH]; // partial out = sum_{j<4} t_j @ (sc_j*Wout)

// ---------------- helpers ----------------
__device__ __forceinline__ uint32_t tanh_h2(uint32_t x) {
    uint32_t r;
    asm("tanh.approx.f16x2 %0, %1;" : "=r"(r) : "r"(x));
    return r;
}
__device__ __forceinline__ uint32_t packf2h2(float lo, float hi) {
    uint32_t r;
    asm("cvt.rn.f16x2.f32 %0, %1, %2;" : "=r"(r) : "f"(hi), "f"(lo));
    return r;
}
__device__ __forceinline__ float2 h2f2(uint32_t h) {
    __half2 v = *(__half2*)&h;
    return __half22float2(v);
}
__device__ __forceinline__ void mma_f16(float c[4],
                                        uint32_t a0, uint32_t a1, uint32_t a2, uint32_t a3,
                                        uint32_t b0, uint32_t b1) {
    asm volatile(
        "mma.sync.aligned.m16n8k16.row.col.f32.f16.f16.f32 "
        "{%0,%1,%2,%3}, {%4,%5,%6,%7}, {%8,%9}, {%0,%1,%2,%3};\n"
        : "+f"(c[0]), "+f"(c[1]), "+f"(c[2]), "+f"(c[3])
        : "r"(a0), "r"(a1), "r"(a2), "r"(a3), "r"(b0), "r"(b1));
}
__device__ __forceinline__ uint32_t pack_h2(float a, float b) {
    __half2 h = __floats2half2_rn(a, b);
    return *(uint32_t*)&h;
}
// logical half2-word for storage word s (0..31)
__device__ __forceinline__ int wof(int s) {
    return 8 * ((s & 7) >> 1) + (s >> 3) + 4 * (s & 1);
}

// ---------------- small kernels ----------------
__global__ void zero_kernel() {
    int t = threadIdx.x + blockIdx.x * blockDim.x;
    if (t < 6 * 2 * 64) ((float*)g_sums)[t] = 0.0f;
}

__global__ __launch_bounds__(256) void xstats_kernel(const float* __restrict__ x) {
    __shared__ float sm[8];
    int tid = threadIdx.x;
    if (tid < 8) sm[tid] = 0.0f;
    __syncthreads();
    float s[4] = {0.f, 0.f, 0.f, 0.f}, q[4] = {0.f, 0.f, 0.f, 0.f};
    const float4* x4 = (const float4*)x;
    size_t base = (size_t)blockIdx.x * 256 + tid;
    #pragma unroll
    for (int i = 0; i < 4; i++) {
        float4 v = x4[base + (size_t)i * 262144];
        s[0] += v.x; q[0] += v.x * v.x;
        s[1] += v.y; q[1] += v.y * v.y;
        s[2] += v.z; q[2] += v.z * v.z;
        s[3] += v.w; q[3] += v.w * v.w;
    }
    #pragma unroll
    for (int k = 0; k < 4; k++)
        for (int off = 16; off; off >>= 1) {
            s[k] += __shfl_xor_sync(0xffffffffu, s[k], off);
            q[k] += __shfl_xor_sync(0xffffffffu, q[k], off);
        }
    if ((tid & 31) == 0) {
        #pragma unroll
        for (int k = 0; k < 4; k++) {
            atomicAdd(&sm[k], s[k]);
            atomicAdd(&sm[4 + k], q[k]);
        }
    }
    __syncthreads();
    if (tid < 8) atomicAdd(&g_sums[0][tid >> 2][tid & 3], sm[tid]);
}

__global__ void fin_kernel(int idx, const float* __restrict__ gamma,
                           const float* __restrict__ beta, int count) {
    int t = threadIdx.x;
    if (t >= count) return;
    const float invN = 1.0f / 1048576.0f;
    float mu  = g_sums[idx][0][t] * invN;
    float var = g_sums[idx][1][t] * invN - mu * mu;
    float sc = gamma[t] * rsqrtf(var + 1e-5f);
    g_aff[idx][0][t] = sc;
    g_aff[idx][1][t] = beta[t] - mu * sc;
}

// prep for mid layer m:
//  blocks [0, m*4)        : Weff_{j} = diag(sc_{j+1}) @ W  -> g_Bfrag (hi/lo fp16)
//  block  m*4             : combined bias
//  blocks (m*4, m*4+4]    : OBfrag[m-1]
__global__ void prep_kernel(int m, const float* __restrict__ W, const float* __restrict__ b,
                            const float* __restrict__ Wout) {
    int blk = blockIdx.x;
    int t = threadIdx.x;
    if (blk == m * 4) {
        int n = t;
        if (n < 64) {
            float acc = b[n];
            for (int j = 0; j < m; j++)
                for (int k = 0; k < 64; k++)
                    acc += g_aff[1 + j][1][k] * W[k * 64 + n];
            g_cbias[n] = acc;
        }
        return;
    }
    if (blk > m * 4) {
        if (t >= 32) return;
        int k4 = blk - m * 4 - 1;
        int jo = m - 1;
        int lane = t, gid = lane >> 2, tig = lane & 3;
        int n = gid;
        int kb = k4 * 16 + 2 * tig;
        float w0 = 0.f, w1 = 0.f, w8 = 0.f, w9 = 0.f;
        if (n < 3) {
            w0 = g_aff[1 + jo][0][kb]     * Wout[kb * 3 + n];
            w1 = g_aff[1 + jo][0][kb + 1] * Wout[(kb + 1) * 3 + n];
            w8 = g_aff[1 + jo][0][kb + 8] * Wout[(kb + 8) * 3 + n];
            w9 = g_aff[1 + jo][0][kb + 9] * Wout[(kb + 9) * 3 + n];
        }
        __half h0 = __float2half_rn(w0), h1 = __float2half_rn(w1);
        __half h8 = __float2half_rn(w8), h9 = __float2half_rn(w9);
        uint4 v;
        { __half2 p0 = __halves2half2(h0, h1); v.x = *(uint32_t*)&p0;
          __half2 p1 = __halves2half2(h8, h9); v.y = *(uint32_t*)&p1; }
        v.z = pack_h2(w0 - __half2float(h0), w1 - __half2float(h1));
        v.w = pack_h2(w8 - __half2float(h8), w9 - __half2float(h9));
        g_OBfrag[(jo * 4 + k4) * 32 + lane] = v;
        return;
    }
    int j = blk >> 2, k4 = blk & 3;
    int n8 = t >> 5, lane = t & 31, gid = lane >> 2, tig = lane & 3;
    int n = n8 * 8 + gid;
    int kb = k4 * 16 + 2 * tig;
    float w0 = g_aff[1 + j][0][kb]     * W[kb * 64 + n];
    float w1 = g_aff[1 + j][0][kb + 1] * W[(kb + 1) * 64 + n];
    float w8 = g_aff[1 + j][0][kb + 8] * W[(kb + 8) * 64 + n];
    float w9 = g_aff[1 + j][0][kb + 9] * W[(kb + 9) * 64 + n];
    __half h0 = __float2half_rn(w0), h1 = __float2half_rn(w1);
    __half h8 = __float2half_rn(w8), h9 = __float2half_rn(w9);
    uint4 v;
    { __half2 p0 = __halves2half2(h0, h1); v.x = *(uint32_t*)&p0;
      __half2 p1 = __halves2half2(h8, h9); v.y = *(uint32_t*)&p1; }
    v.z = pack_h2(w0 - __half2float(h0), w1 - __half2float(h1));
    v.w = pack_h2(w8 - __half2float(h8), w9 - __half2float(h9));
    g_Bfrag[((j * 4 + k4) * 8 + n8) * 32 + lane] = v;
}

// after fin(5): OBfrag[4] (blocks 0-3) + bout2 (block 4)
__global__ void prepout_kernel(const float* __restrict__ Wout, const float* __restrict__ bout) {
    int blk = blockIdx.x, t = threadIdx.x;
    if (blk == 4) {
        __shared__ float acc[3];
        if (t < 3) acc[t] = bout[t];
        __syncthreads();
        if (t < 64) {
            float sh = 0.f;
            #pragma unroll
            for (int j = 0; j < 5; j++) sh += g_aff[1 + j][1][t];
            atomicAdd(&acc[0], sh * Wout[t * 3 + 0]);
            atomicAdd(&acc[1], sh * Wout[t * 3 + 1]);
            atomicAdd(&acc[2], sh * Wout[t * 3 + 2]);
        }
        __syncthreads();
        if (t < 3) g_bout2[t] = acc[t];
        return;
    }
    if (t >= 32) return;
    int k4 = blk;
    int lane = t, gid = lane >> 2, tig = lane & 3;
    int n = gid;
    int kb = k4 * 16 + 2 * tig;
    float w0 = 0.f, w1 = 0.f, w8 = 0.f, w9 = 0.f;
    if (n < 3) {
        w0 = g_aff[5][0][kb]     * Wout[kb * 3 + n];
        w1 = g_aff[5][0][kb + 1] * Wout[(kb + 1) * 3 + n];
        w8 = g_aff[5][0][kb + 8] * Wout[(kb + 8) * 3 + n];
        w9 = g_aff[5][0][kb + 9] * Wout[(kb + 9) * 3 + n];
    }
    __half h0 = __float2half_rn(w0), h1 = __float2half_rn(w1);
    __half h8 = __float2half_rn(w8), h9 = __float2half_rn(w9);
    uint4 v;
    { __half2 p0 = __halves2half2(h0, h1); v.x = *(uint32_t*)&p0;
      __half2 p1 = __halves2half2(h8, h9); v.y = *(uint32_t*)&p1; }
    v.z = pack_h2(w0 - __half2float(h0), w1 - __half2float(h1));
    v.w = pack_h2(w8 - __half2float(h8), w9 - __half2float(h9));
    g_OBfrag[(4 * 4 + k4) * 32 + lane] = v;
}

// first layer: t0 = tanh(bn0(x) @ W0 + b0); stats -> g_sums[1]. 128 rows/CTA.
__global__ __launch_bounds__(256) void k1_kernel(const float* __restrict__ x,
                                                 const float* __restrict__ W0,
                                                 const float* __restrict__ b0) {
    __shared__ float Ws[4][64];
    __shared__ float s_sum[64], s_sq[64];
    __shared__ float affs[4], affb[4];
    int tid = threadIdx.x;
    if (tid < 256) Ws[tid >> 6][tid & 63] = W0[tid];
    if (tid < 64) { s_sum[tid] = 0.f; s_sq[tid] = 0.f; }
    if (tid < 4) { affs[tid] = g_aff[0][0][tid]; affb[tid] = g_aff[0][1][tid]; }
    __syncthreads();

    int q = tid & 7, sub = tid >> 3;
    int cols[8];
    #pragma unroll
    for (int e = 0; e < 4; e++) {
        int w = wof(q * 4 + e);
        cols[2 * e] = 2 * w; cols[2 * e + 1] = 2 * w + 1;
    }
    float wk0[8], wk1[8], wk2[8], wk3[8], bb[8];
    #pragma unroll
    for (int i = 0; i < 8; i++) {
        wk0[i] = Ws[0][cols[i]]; wk1[i] = Ws[1][cols[i]];
        wk2[i] = Ws[2][cols[i]]; wk3[i] = Ws[3][cols[i]];
        bb[i] = b0[cols[i]];
    }
    float a0s = affs[0], a1s = affs[1], a2s = affs[2], a3s = affs[3];
    float a0b = affb[0], a1b = affb[1], a2b = affb[2], a3b = affb[3];
    float s[8], qq[8];
    #pragma unroll
    for (int i = 0; i < 8; i++) { s[i] = 0.f; qq[i] = 0.f; }

    size_t row0 = (size_t)blockIdx.x * 128;
    const float4* x4 = (const float4*)x;
    uint4* outp = (uint4*)g_t;

    #pragma unroll
    for (int it = 0; it < 4; it++) {
        size_t r = row0 + it * 32 + sub;
        float4 xv = x4[r];
        float h0 = xv.x * a0s + a0b;
        float h1 = xv.y * a1s + a1b;
        float h2 = xv.z * a2s + a2b;
        float h3 = xv.w * a3s + a3b;
        uint32_t wrd[4];
        #pragma unroll
        for (int e = 0; e < 4; e++) {
            float z0 = bb[2*e]   + h0*wk0[2*e]   + h1*wk1[2*e]   + h2*wk2[2*e]   + h3*wk3[2*e];
            float z1 = bb[2*e+1] + h0*wk0[2*e+1] + h1*wk1[2*e+1] + h2*wk2[2*e+1] + h3*wk3[2*e+1];
            wrd[e] = tanh_h2(packf2h2(z0, z1));
            float2 f = h2f2(wrd[e]);
            s[2*e] += f.x;  qq[2*e] += f.x * f.x;
            s[2*e+1] += f.y; qq[2*e+1] += f.y * f.y;
        }
        outp[r * 8 + q] = make_uint4(wrd[0], wrd[1], wrd[2], wrd[3]);
    }

    #pragma unroll
    for (int i = 0; i < 8; i++) {
        s[i]  += __shfl_xor_sync(0xffffffffu, s[i], 8);
        qq[i] += __shfl_xor_sync(0xffffffffu, qq[i], 8);
        s[i]  += __shfl_xor_sync(0xffffffffu, s[i], 16);
        qq[i] += __shfl_xor_sync(0xffffffffu, qq[i], 16);
    }
    if ((tid & 24) == 0) {
        #pragma unroll
        for (int i = 0; i < 8; i++) {
            atomicAdd(&s_sum[cols[i]], s[i]);
            atomicAdd(&s_sq[cols[i]], qq[i]);
        }
    }
    __syncthreads();
    if (tid < 64) {
        atomicAdd(&g_sums[1][0][tid], s_sum[tid]);
        atomicAdd(&g_sums[1][1][tid], s_sq[tid]);
    }
}

// mid layer m: z = sum_{j<m} t_j @ Weff_j + c; t_m = tanh(z); stats -> g_sums[m+1]
// 128 rows/CTA (one m16 row-block per warp), grid 8192, 3 CTAs/SM.
// FUSE (m==4): also accumulate partial out -> g_pout
template <int M, bool FUSE>
__global__ void __launch_bounds__(256, 3) midk(int mslot) {
    __shared__ float s_sum[64], s_sq[64];
    int tid = threadIdx.x, warp = tid >> 5, lane = tid & 31;
    int gid = lane >> 2, tig = lane & 3;
    if (tid < 64) { s_sum[tid] = 0.f; s_sq[tid] = 0.f; }

    float C[8][4];
    #pragma unroll
    for (int n8 = 0; n8 < 8; n8++)
        #pragma unroll
        for (int e = 0; e < 4; e++) C[n8][e] = 0.f;
    float Co[4];
    if (FUSE) {
        #pragma unroll
        for (int e = 0; e < 4; e++) Co[e] = 0.f;
    }

    size_t R0 = (size_t)blockIdx.x * 128;
    size_t rb = R0 + warp * 16 + gid;

    #pragma unroll
    for (int j = 0; j < M; j++) {
        const uint4* tp = (const uint4*)(g_t + (size_t)j * BATCH * HID);
        uint4 A[2][2];
        #pragma unroll
        for (int rh = 0; rh < 2; rh++) {
            size_t base = (rb + rh * 8) * 8 + tig * 2;
            A[rh][0] = tp[base];
            A[rh][1] = tp[base + 1];
        }
        #pragma unroll
        for (int k4 = 0; k4 < 4; k4++) {
            uint4 lo = A[0][k4 >> 1];
            uint4 hi = A[1][k4 >> 1];
            uint32_t a0 = (k4 & 1) ? lo.z : lo.x;
            uint32_t a2 = (k4 & 1) ? lo.w : lo.y;
            uint32_t a1 = (k4 & 1) ? hi.z : hi.x;
            uint32_t a3 = (k4 & 1) ? hi.w : hi.y;
            #pragma unroll
            for (int n8 = 0; n8 < 8; n8++) {
                uint4 bf = g_Bfrag[((j * 4 + k4) * 8 + n8) * 32 + lane];
                mma_f16(C[n8], a0, a1, a2, a3, bf.x, bf.y);  // hi
                mma_f16(C[n8], a0, a1, a2, a3, bf.z, bf.w);  // lo
            }
            if (FUSE) {
                uint4 of = g_OBfrag[(j * 4 + k4) * 32 + lane];
                mma_f16(Co, a0, a1, a2, a3, of.x, of.y);
                mma_f16(Co, a0, a1, a2, a3, of.z, of.w);
            }
        }
    }

    // ---- epilogue: bias + tanh.f16x2 + packed store + stats ----
    uint4* toutp = (uint4*)(g_t + (size_t)mslot * BATCH * HID);
    float ssum[16], ssq[16];
    #pragma unroll
    for (int i = 0; i < 16; i++) { ssum[i] = 0.f; ssq[i] = 0.f; }

    {
        uint32_t w0[8], w1[8];
        #pragma unroll
        for (int n8 = 0; n8 < 8; n8++) {
            int col = n8 * 8 + tig * 2;
            float b0 = g_cbias[col], b1 = g_cbias[col + 1];
            uint32_t h0 = tanh_h2(packf2h2(C[n8][0] + b0, C[n8][1] + b1));
            uint32_t h1 = tanh_h2(packf2h2(C[n8][2] + b0, C[n8][3] + b1));
            w0[n8] = h0; w1[n8] = h1;
            float2 f0 = h2f2(h0), f1 = h2f2(h1);
            ssum[2*n8]   += f0.x + f1.x;  ssq[2*n8]   += f0.x*f0.x + f1.x*f1.x;
            ssum[2*n8+1] += f0.y + f1.y;  ssq[2*n8+1] += f0.y*f0.y + f1.y*f1.y;
        }
        size_t r = rb;
        toutp[r * 8 + tig * 2]           = make_uint4(w0[0], w0[1], w0[2], w0[3]);
        toutp[r * 8 + tig * 2 + 1]       = make_uint4(w0[4], w0[5], w0[6], w0[7]);
        toutp[(r + 8) * 8 + tig * 2]     = make_uint4(w1[0], w1[1], w1[2], w1[3]);
        toutp[(r + 8) * 8 + tig * 2 + 1] = make_uint4(w1[4], w1[5], w1[6], w1[7]);
    }

    if (FUSE) {
        size_t r = rb;
        int n = 2 * tig;
        if (n < 3) {
            g_pout[r * 3 + n]       = Co[0];
            g_pout[(r + 8) * 3 + n] = Co[2];
        }
        if (n + 1 < 3) {
            g_pout[r * 3 + n + 1]       = Co[1];
            g_pout[(r + 8) * 3 + n + 1] = Co[3];
        }
    }

    #pragma unroll
    for (int i = 0; i < 16; i++) {
        ssum[i] += __shfl_xor_sync(0xffffffffu, ssum[i], 4);
        ssq[i]  += __shfl_xor_sync(0xffffffffu, ssq[i], 4);
        ssum[i] += __shfl_xor_sync(0xffffffffu, ssum[i], 8);
        ssq[i]  += __shfl_xor_sync(0xffffffffu, ssq[i], 8);
        ssum[i] += __shfl_xor_sync(0xffffffffu, ssum[i], 16);
        ssq[i]  += __shfl_xor_sync(0xffffffffu, ssq[i], 16);
    }
    __syncthreads();
    if (lane < 4) {
        #pragma unroll
        for (int n8 = 0; n8 < 8; n8++) {
            int col = n8 * 8 + lane * 2;
            atomicAdd(&s_sum[col],     ssum[2 * n8]);
            atomicAdd(&s_sum[col + 1], ssum[2 * n8 + 1]);
            atomicAdd(&s_sq[col],      ssq[2 * n8]);
            atomicAdd(&s_sq[col + 1],  ssq[2 * n8 + 1]);
        }
    }
    __syncthreads();
    if (tid < 64) {
        atomicAdd(&g_sums[mslot + 1][0][tid], s_sum[tid]);
        atomicAdd(&g_sums[mslot + 1][1][tid], s_sq[tid]);
    }
}

// final: out = g_pout + t4 @ (sc4*Wout) + bout2. MMA-based, 128 rows/CTA.
__global__ __launch_bounds__(256) void out2_kernel(float* __restrict__ out) {
    int tid = threadIdx.x, warp = tid >> 5, lane = tid & 31;
    int gid = lane >> 2, tig = lane & 3;
    size_t r = (size_t)blockIdx.x * 128 + warp * 16 + gid;
    int n = 2 * tig;

    float Co[4];
    Co[0] = (n < 3)     ? g_pout[r * 3 + n]           : 0.f;
    Co[1] = (n + 1 < 3) ? g_pout[r * 3 + n + 1]       : 0.f;
    Co[2] = (n < 3)     ? g_pout[(r + 8) * 3 + n]     : 0.f;
    Co[3] = (n + 1 < 3) ? g_pout[(r + 8) * 3 + n + 1] : 0.f;

    const uint4* tp = (const uint4*)(g_t + (size_t)4 * BATCH * HID);
    uint4 A[2][2];
    #pragma unroll
    for (int rh = 0; rh < 2; rh++) {
        size_t base = (r + rh * 8) * 8 + tig * 2;
        A[rh][0] = tp[base];
        A[rh][1] = tp[base + 1];
    }
    #pragma unroll
    for (int k4 = 0; k4 < 4; k4++) {
        uint4 of = g_OBfrag[(4 * 4 + k4) * 32 + lane];
        uint4 lo = A[0][k4 >> 1];
        uint4 hi = A[1][k4 >> 1];
        uint32_t a0 = (k4 & 1) ? lo.z : lo.x;
        uint32_t a2 = (k4 & 1) ? lo.w : lo.y;
        uint32_t a1 = (k4 & 1) ? hi.z : hi.x;
        uint32_t a3 = (k4 & 1) ? hi.w : hi.y;
        mma_f16(Co, a0, a1, a2, a3, of.x, of.y);
        mma_f16(Co, a0, a1, a2, a3, of.z, of.w);
    }

    if (n < 3) {
        float bo = g_bout2[n];
        out[r * 3 + n]       = Co[0] + bo;
        out[(r + 8) * 3 + n] = Co[2] + bo;
    }
    if (n + 1 < 3) {
        float bo = g_bout2[n + 1];
        out[r * 3 + n + 1]       = Co[1] + bo;
        out[(r + 8) * 3 + n + 1] = Co[3] + bo;
    }
}

// ---------------- launch ----------------
extern "C" void kernel_launch(void* const* d_in, const int* in_sizes, int n_in,
                              void* d_out, int out_size) {
    const float* x    = (const float*)d_in[0];
    const float* bn0g = (const float*)d_in[1];
    const float* bn0b = (const float*)d_in[2];
    const float* W0   = (const float*)d_in[3];
    const float* b0   = (const float*)d_in[4];
    const float* g0   = (const float*)d_in[5];
    const float* be0  = (const float*)d_in[6];
    const float* Wh   = (const float*)d_in[7];
    const float* bh   = (const float*)d_in[8];
    const float* gh   = (const float*)d_in[9];
    const float* beh  = (const float*)d_in[10];
    const float* Wo   = (const float*)d_in[11];
    const float* bo   = (const float*)d_in[12];
    float* out = (float*)d_out;

    zero_kernel<<<3, 256>>>();
    xstats_kernel<<<1024, 256>>>(x);
    fin_kernel<<<1, 64>>>(0, bn0g, bn0b, 4);
    k1_kernel<<<8192, 256>>>(x, W0, b0);
    fin_kernel<<<1, 64>>>(1, g0, be0, 64);

    for (int m = 1; m <= 4; m++) {
        prep_kernel<<<m * 4 + 5, 256>>>(m, Wh + (size_t)(m - 1) * 4096, bh + (m - 1) * 64, Wo);
        switch (m) {
            case 1: midk<1, false><<<8192, 256>>>(m); break;
            case 2: midk<2, false><<<8192, 256>>>(m); break;
            case 3: midk<3, false><<<8192, 256>>>(m); break;
            case 4: midk<4, true ><<<8192, 256>>>(m); break;
        }
        fin_kernel<<<1, 64>>>(m + 1, gh + (m - 1) * 64, beh + (m - 1) * 64, 64);
    }
    prepout_kernel<<<5, 64>>>(Wo, bo);
    out2_kernel<<<8192, 256>>>(out);
}

// round 12
// speedup vs baseline: 1.3769x; 1.3769x over previous
#include <cuda_runtime.h>
#include <cuda_fp16.h>
#include <cstdint>

#define BATCH 1048576
#define HID 64

// ---------------- device-global scratch ----------------
// t_j stored in PERMUTED word layout (fragment-native, see midk A-loads)
__device__ __half g_t[(size_t)5 * BATCH * HID];
__device__ float  g_sums[6][2][64];
__device__ float  g_aff [6][2][64];
// B fragments, hi-only fp16, packed 2 n8-fragments per uint4:
// [j][k4][p][lane], p in 0..3: (x,y) = frag n8=2p, (z,w) = frag n8=2p+1
__device__ uint4  g_Bfrag[4 * 4 * 4 * 32];
__device__ uint2  g_OBfrag[5 * 4 * 32];      // [j][k4][lane] out-tile frags (hi-only)
__device__ float  g_cbias[64];
__device__ float  g_bout2[3];
__device__ float  g_pout[(size_t)3 * BATCH]; // partial out = sum_{j<4} t_j @ (sc_j*Wout)

// ---------------- helpers ----------------
__device__ __forceinline__ uint32_t tanh_h2(uint32_t x) {
    uint32_t r;
    asm("tanh.approx.f16x2 %0, %1;" : "=r"(r) : "r"(x));
    return r;
}
__device__ __forceinline__ uint32_t packf2h2(float lo, float hi) {
    uint32_t r;
    asm("cvt.rn.f16x2.f32 %0, %1, %2;" : "=r"(r) : "f"(hi), "f"(lo));
    return r;
}
__device__ __forceinline__ float2 h2f2(uint32_t h) {
    __half2 v = *(__half2*)&h;
    return __half22float2(v);
}
__device__ __forceinline__ void mma_f16(float c[4],
                                        uint32_t a0, uint32_t a1, uint32_t a2, uint32_t a3,
                                        uint32_t b0, uint32_t b1) {
    asm volatile(
        "mma.sync.aligned.m16n8k16.row.col.f32.f16.f16.f32 "
        "{%0,%1,%2,%3}, {%4,%5,%6,%7}, {%8,%9}, {%0,%1,%2,%3};\n"
        : "+f"(c[0]), "+f"(c[1]), "+f"(c[2]), "+f"(c[3])
        : "r"(a0), "r"(a1), "r"(a2), "r"(a3), "r"(b0), "r"(b1));
}
__device__ __forceinline__ uint32_t pack2h(float a, float b) {
    __half2 h = __halves2half2(__float2half_rn(a), __float2half_rn(b));
    return *(uint32_t*)&h;
}
// fp16 rounding residual
__device__ __forceinline__ float flo(float w) {
    return w - __half2float(__float2half_rn(w));
}
// logical half2-word for storage word s (0..31)
__device__ __forceinline__ int wof(int s) {
    return 8 * ((s & 7) >> 1) + (s >> 3) + 4 * (s & 1);
}

// ---------------- small kernels ----------------
__global__ void zero_kernel() {
    int t = threadIdx.x + blockIdx.x * blockDim.x;
    if (t < 6 * 2 * 64) ((float*)g_sums)[t] = 0.0f;
}

__global__ __launch_bounds__(256) void xstats_kernel(const float* __restrict__ x) {
    __shared__ float sm[8];
    int tid = threadIdx.x;
    if (tid < 8) sm[tid] = 0.0f;
    __syncthreads();
    float s[4] = {0.f, 0.f, 0.f, 0.f}, q[4] = {0.f, 0.f, 0.f, 0.f};
    const float4* x4 = (const float4*)x;
    size_t base = (size_t)blockIdx.x * 256 + tid;
    #pragma unroll
    for (int i = 0; i < 4; i++) {
        float4 v = x4[base + (size_t)i * 262144];
        s[0] += v.x; q[0] += v.x * v.x;
        s[1] += v.y; q[1] += v.y * v.y;
        s[2] += v.z; q[2] += v.z * v.z;
        s[3] += v.w; q[3] += v.w * v.w;
    }
    #pragma unroll
    for (int k = 0; k < 4; k++)
        for (int off = 16; off; off >>= 1) {
            s[k] += __shfl_xor_sync(0xffffffffu, s[k], off);
            q[k] += __shfl_xor_sync(0xffffffffu, q[k], off);
        }
    if ((tid & 31) == 0) {
        #pragma unroll
        for (int k = 0; k < 4; k++) {
            atomicAdd(&sm[k], s[k]);
            atomicAdd(&sm[4 + k], q[k]);
        }
    }
    __syncthreads();
    if (tid < 8) atomicAdd(&g_sums[0][tid >> 2][tid & 3], sm[tid]);
}

__global__ void fin_kernel(int idx, const float* __restrict__ gamma,
                           const float* __restrict__ beta, int count) {
    int t = threadIdx.x;
    if (t >= count) return;
    const float invN = 1.0f / 1048576.0f;
    float mu  = g_sums[idx][0][t] * invN;
    float var = g_sums[idx][1][t] * invN - mu * mu;
    float sc = gamma[t] * rsqrtf(var + 1e-5f);
    g_aff[idx][0][t] = sc;
    g_aff[idx][1][t] = beta[t] - mu * sc;
}

// prep for mid layer m:
//  blocks [0, m*4)      : Whi_{j} = fp16(diag(sc_{j+1}) @ W) -> g_Bfrag (packed pairs)
//  block  m*4           : combined bias incl. mean-compensation of dropped lo term
//  blocks (m*4, m*4+4]  : OBfrag[m-1] (hi-only)
__global__ void prep_kernel(int m, const float* __restrict__ W, const float* __restrict__ b,
                            const float* __restrict__ Wout) {
    int blk = blockIdx.x;
    int t = threadIdx.x;
    const float invN = 1.0f / 1048576.0f;
    if (blk == m * 4) {
        int n = t;
        if (n < 64) {
            float acc = b[n];
            for (int j = 0; j < m; j++)
                for (int k = 0; k < 64; k++) {
                    float w = W[k * 64 + n];
                    float weff = g_aff[1 + j][0][k] * w;
                    float mu = g_sums[1 + j][0][k] * invN;
                    acc += g_aff[1 + j][1][k] * w + mu * flo(weff);
                }
            g_cbias[n] = acc;
        }
        return;
    }
    if (blk > m * 4) {
        if (t >= 32) return;
        int k4 = blk - m * 4 - 1;
        int jo = m - 1;
        int lane = t, gid = lane >> 2, tig = lane & 3;
        int n = gid;
        int kb = k4 * 16 + 2 * tig;
        float w0 = 0.f, w1 = 0.f, w8 = 0.f, w9 = 0.f;
        if (n < 3) {
            w0 = g_aff[1 + jo][0][kb]     * Wout[kb * 3 + n];
            w1 = g_aff[1 + jo][0][kb + 1] * Wout[(kb + 1) * 3 + n];
            w8 = g_aff[1 + jo][0][kb + 8] * Wout[(kb + 8) * 3 + n];
            w9 = g_aff[1 + jo][0][kb + 9] * Wout[(kb + 9) * 3 + n];
        }
        g_OBfrag[(jo * 4 + k4) * 32 + lane] = make_uint2(pack2h(w0, w1), pack2h(w8, w9));
        return;
    }
    // B fragments: 128 threads used, p = t>>5 packs n8 = 2p, 2p+1
    if (t >= 128) return;
    int j = blk >> 2, k4 = blk & 3;
    int p = t >> 5, lane = t & 31, gid = lane >> 2, tig = lane & 3;
    int kb = k4 * 16 + 2 * tig;
    float sc0 = g_aff[1 + j][0][kb],     sc1 = g_aff[1 + j][0][kb + 1];
    float sc8 = g_aff[1 + j][0][kb + 8], sc9 = g_aff[1 + j][0][kb + 9];
    uint4 v;
    {
        int n = (2 * p) * 8 + gid;
        v.x = pack2h(sc0 * W[kb * 64 + n],       sc1 * W[(kb + 1) * 64 + n]);
        v.y = pack2h(sc8 * W[(kb + 8) * 64 + n], sc9 * W[(kb + 9) * 64 + n]);
    }
    {
        int n = (2 * p + 1) * 8 + gid;
        v.z = pack2h(sc0 * W[kb * 64 + n],       sc1 * W[(kb + 1) * 64 + n]);
        v.w = pack2h(sc8 * W[(kb + 8) * 64 + n], sc9 * W[(kb + 9) * 64 + n]);
    }
    g_Bfrag[((j * 4 + k4) * 4 + p) * 32 + lane] = v;
}

// after fin(5): OBfrag[4] (blocks 0-3) + bout2 with lo-mean comp for all j (block 4)
__global__ void prepout_kernel(const float* __restrict__ Wout, const float* __restrict__ bout) {
    int blk = blockIdx.x, t = threadIdx.x;
    const float invN = 1.0f / 1048576.0f;
    if (blk == 4) {
        __shared__ float acc[3];
        if (t < 3) acc[t] = bout[t];
        __syncthreads();
        if (t < 64) {
            float sh = 0.f;
            #pragma unroll
            for (int j = 0; j < 5; j++) sh += g_aff[1 + j][1][t];
            float c0 = sh * Wout[t * 3 + 0];
            float c1 = sh * Wout[t * 3 + 1];
            float c2 = sh * Wout[t * 3 + 2];
            #pragma unroll
            for (int j = 0; j < 5; j++) {
                float sc = g_aff[1 + j][0][t];
                float mu = g_sums[1 + j][0][t] * invN;
                c0 += mu * flo(sc * Wout[t * 3 + 0]);
                c1 += mu * flo(sc * Wout[t * 3 + 1]);
                c2 += mu * flo(sc * Wout[t * 3 + 2]);
            }
            atomicAdd(&acc[0], c0);
            atomicAdd(&acc[1], c1);
            atomicAdd(&acc[2], c2);
        }
        __syncthreads();
        if (t < 3) g_bout2[t] = acc[t];
        return;
    }
    if (t >= 32) return;
    int k4 = blk;
    int lane = t, gid = lane >> 2, tig = lane & 3;
    int n = gid;
    int kb = k4 * 16 + 2 * tig;
    float w0 = 0.f, w1 = 0.f, w8 = 0.f, w9 = 0.f;
    if (n < 3) {
        w0 = g_aff[5][0][kb]     * Wout[kb * 3 + n];
        w1 = g_aff[5][0][kb + 1] * Wout[(kb + 1) * 3 + n];
        w8 = g_aff[5][0][kb + 8] * Wout[(kb + 8) * 3 + n];
        w9 = g_aff[5][0][kb + 9] * Wout[(kb + 9) * 3 + n];
    }
    g_OBfrag[(4 * 4 + k4) * 32 + lane] = make_uint2(pack2h(w0, w1), pack2h(w8, w9));
}

// first layer: t0 = tanh(bn0(x) @ W0 + b0); stats -> g_sums[1]. 128 rows/CTA.
__global__ __launch_bounds__(256) void k1_kernel(const float* __restrict__ x,
                                                 const float* __restrict__ W0,
                                                 const float* __restrict__ b0) {
    __shared__ float Ws[4][64];
    __shared__ float s_sum[64], s_sq[64];
    __shared__ float affs[4], affb[4];
    int tid = threadIdx.x;
    if (tid < 256) Ws[tid >> 6][tid & 63] = W0[tid];
    if (tid < 64) { s_sum[tid] = 0.f; s_sq[tid] = 0.f; }
    if (tid < 4) { affs[tid] = g_aff[0][0][tid]; affb[tid] = g_aff[0][1][tid]; }
    __syncthreads();

    int q = tid & 7, sub = tid >> 3;
    int cols[8];
    #pragma unroll
    for (int e = 0; e < 4; e++) {
        int w = wof(q * 4 + e);
        cols[2 * e] = 2 * w; cols[2 * e + 1] = 2 * w + 1;
    }
    float wk0[8], wk1[8], wk2[8], wk3[8], bb[8];
    #pragma unroll
    for (int i = 0; i < 8; i++) {
        wk0[i] = Ws[0][cols[i]]; wk1[i] = Ws[1][cols[i]];
        wk2[i] = Ws[2][cols[i]]; wk3[i] = Ws[3][cols[i]];
        bb[i] = b0[cols[i]];
    }
    float a0s = affs[0], a1s = affs[1], a2s = affs[2], a3s = affs[3];
    float a0b = affb[0], a1b = affb[1], a2b = affb[2], a3b = affb[3];
    float s[8], qq[8];
    #pragma unroll
    for (int i = 0; i < 8; i++) { s[i] = 0.f; qq[i] = 0.f; }

    size_t row0 = (size_t)blockIdx.x * 128;
    const float4* x4 = (const float4*)x;
    uint4* outp = (uint4*)g_t;

    #pragma unroll
    for (int it = 0; it < 4; it++) {
        size_t r = row0 + it * 32 + sub;
        float4 xv = x4[r];
        float h0 = xv.x * a0s + a0b;
        float h1 = xv.y * a1s + a1b;
        float h2 = xv.z * a2s + a2b;
        float h3 = xv.w * a3s + a3b;
        uint32_t wrd[4];
        #pragma unroll
        for (int e = 0; e < 4; e++) {
            float z0 = bb[2*e]   + h0*wk0[2*e]   + h1*wk1[2*e]   + h2*wk2[2*e]   + h3*wk3[2*e];
            float z1 = bb[2*e+1] + h0*wk0[2*e+1] + h1*wk1[2*e+1] + h2*wk2[2*e+1] + h3*wk3[2*e+1];
            wrd[e] = tanh_h2(packf2h2(z0, z1));
            float2 f = h2f2(wrd[e]);
            s[2*e] += f.x;  qq[2*e] += f.x * f.x;
            s[2*e+1] += f.y; qq[2*e+1] += f.y * f.y;
        }
        outp[r * 8 + q] = make_uint4(wrd[0], wrd[1], wrd[2], wrd[3]);
    }

    #pragma unroll
    for (int i = 0; i < 8; i++) {
        s[i]  += __shfl_xor_sync(0xffffffffu, s[i], 8);
        qq[i] += __shfl_xor_sync(0xffffffffu, qq[i], 8);
        s[i]  += __shfl_xor_sync(0xffffffffu, s[i], 16);
        qq[i] += __shfl_xor_sync(0xffffffffu, qq[i], 16);
    }
    if ((tid & 24) == 0) {
        #pragma unroll
        for (int i = 0; i < 8; i++) {
            atomicAdd(&s_sum[cols[i]], s[i]);
            atomicAdd(&s_sq[cols[i]], qq[i]);
        }
    }
    __syncthreads();
    if (tid < 64) {
        atomicAdd(&g_sums[1][0][tid], s_sum[tid]);
        atomicAdd(&g_sums[1][1][tid], s_sq[tid]);
    }
}

// mid layer m: z = sum_{j<m} t_j @ Whi_j + c; t_m = tanh(z); stats -> g_sums[m+1]
// 256 rows/CTA (s=2), grid 4096, 2 CTAs/SM (proven R8 shape). Hi-only MMAs.
// FUSE (m==4): also accumulate partial out -> g_pout
template <int M, bool FUSE>
__global__ void __launch_bounds__(256, 2) midk(int mslot) {
    __shared__ float s_sum[64], s_sq[64];
    int tid = threadIdx.x, warp = tid >> 5, lane = tid & 31;
    int gid = lane >> 2, tig = lane & 3;
    if (tid < 64) { s_sum[tid] = 0.f; s_sq[tid] = 0.f; }

    float C[2][8][4];
    #pragma unroll
    for (int s = 0; s < 2; s++)
        #pragma unroll
        for (int n8 = 0; n8 < 8; n8++)
            #pragma unroll
            for (int e = 0; e < 4; e++) C[s][n8][e] = 0.f;
    float Co[2][4];
    if (FUSE) {
        #pragma unroll
        for (int s = 0; s < 2; s++)
            #pragma unroll
            for (int e = 0; e < 4; e++) Co[s][e] = 0.f;
    }

    size_t R0 = (size_t)blockIdx.x * 256;
    size_t rb[2] = { R0 + warp * 16 + gid, R0 + 128 + warp * 16 + gid };

    #pragma unroll
    for (int j = 0; j < M; j++) {
        const uint4* tp = (const uint4*)(g_t + (size_t)j * BATCH * HID);
        uint4 A[2][2][2];
        #pragma unroll
        for (int s = 0; s < 2; s++)
            #pragma unroll
            for (int rh = 0; rh < 2; rh++) {
                size_t base = (rb[s] + rh * 8) * 8 + tig * 2;
                A[s][rh][0] = tp[base];
                A[s][rh][1] = tp[base + 1];
            }
        #pragma unroll
        for (int k4 = 0; k4 < 4; k4++) {
            #pragma unroll
            for (int p = 0; p < 4; p++) {
                uint4 bv = g_Bfrag[((j * 4 + k4) * 4 + p) * 32 + lane];
                #pragma unroll
                for (int s = 0; s < 2; s++) {
                    uint4 lo = A[s][0][k4 >> 1];
                    uint4 hi = A[s][1][k4 >> 1];
                    uint32_t a0 = (k4 & 1) ? lo.z : lo.x;
                    uint32_t a2 = (k4 & 1) ? lo.w : lo.y;
                    uint32_t a1 = (k4 & 1) ? hi.z : hi.x;
                    uint32_t a3 = (k4 & 1) ? hi.w : hi.y;
                    mma_f16(C[s][2 * p],     a0, a1, a2, a3, bv.x, bv.y);
                    mma_f16(C[s][2 * p + 1], a0, a1, a2, a3, bv.z, bv.w);
                }
            }
            if (FUSE) {
                uint2 of = g_OBfrag[(j * 4 + k4) * 32 + lane];
                #pragma unroll
                for (int s = 0; s < 2; s++) {
                    uint4 lo = A[s][0][k4 >> 1];
                    uint4 hi = A[s][1][k4 >> 1];
                    uint32_t a0 = (k4 & 1) ? lo.z : lo.x;
                    uint32_t a2 = (k4 & 1) ? lo.w : lo.y;
                    uint32_t a1 = (k4 & 1) ? hi.z : hi.x;
                    uint32_t a3 = (k4 & 1) ? hi.w : hi.y;
                    mma_f16(Co[s], a0, a1, a2, a3, of.x, of.y);
                }
            }
        }
    }

    // ---- epilogue: bias + tanh.f16x2 + packed store + stats ----
    uint4* toutp = (uint4*)(g_t + (size_t)mslot * BATCH * HID);
    float ssum[16], ssq[16];
    #pragma unroll
    for (int i = 0; i < 16; i++) { ssum[i] = 0.f; ssq[i] = 0.f; }

    #pragma unroll
    for (int s = 0; s < 2; s++) {
        uint32_t w0[8], w1[8];
        #pragma unroll
        for (int n8 = 0; n8 < 8; n8++) {
            int col = n8 * 8 + tig * 2;
            float b0 = g_cbias[col], b1 = g_cbias[col + 1];
            uint32_t h0 = tanh_h2(packf2h2(C[s][n8][0] + b0, C[s][n8][1] + b1));
            uint32_t h1 = tanh_h2(packf2h2(C[s][n8][2] + b0, C[s][n8][3] + b1));
            w0[n8] = h0; w1[n8] = h1;
            float2 f0 = h2f2(h0), f1 = h2f2(h1);
            ssum[2*n8]   += f0.x + f1.x;  ssq[2*n8]   += f0.x*f0.x + f1.x*f1.x;
            ssum[2*n8+1] += f0.y + f1.y;  ssq[2*n8+1] += f0.y*f0.y + f1.y*f1.y;
        }
        size_t r = rb[s];
        toutp[r * 8 + tig * 2]           = make_uint4(w0[0], w0[1], w0[2], w0[3]);
        toutp[r * 8 + tig * 2 + 1]       = make_uint4(w0[4], w0[5], w0[6], w0[7]);
        toutp[(r + 8) * 8 + tig * 2]     = make_uint4(w1[0], w1[1], w1[2], w1[3]);
        toutp[(r + 8) * 8 + tig * 2 + 1] = make_uint4(w1[4], w1[5], w1[6], w1[7]);
    }

    if (FUSE) {
        #pragma unroll
        for (int s = 0; s < 2; s++) {
            size_t r = rb[s];
            int n = 2 * tig;
            if (n < 3) {
                g_pout[r * 3 + n]       = Co[s][0];
                g_pout[(r + 8) * 3 + n] = Co[s][2];
            }
            if (n + 1 < 3) {
                g_pout[r * 3 + n + 1]       = Co[s][1];
                g_pout[(r + 8) * 3 + n + 1] = Co[s][3];
            }
        }
    }

    #pragma unroll
    for (int i = 0; i < 16; i++) {
        ssum[i] += __shfl_xor_sync(0xffffffffu, ssum[i], 4);
        ssq[i]  += __shfl_xor_sync(0xffffffffu, ssq[i], 4);
        ssum[i] += __shfl_xor_sync(0xffffffffu, ssum[i], 8);
        ssq[i]  += __shfl_xor_sync(0xffffffffu, ssq[i], 8);
        ssum[i] += __shfl_xor_sync(0xffffffffu, ssum[i], 16);
        ssq[i]  += __shfl_xor_sync(0xffffffffu, ssq[i], 16);
    }
    __syncthreads();
    if (lane < 4) {
        #pragma unroll
        for (int n8 = 0; n8 < 8; n8++) {
            int col = n8 * 8 + lane * 2;
            atomicAdd(&s_sum[col],     ssum[2 * n8]);
            atomicAdd(&s_sum[col + 1], ssum[2 * n8 + 1]);
            atomicAdd(&s_sq[col],      ssq[2 * n8]);
            atomicAdd(&s_sq[col + 1],  ssq[2 * n8 + 1]);
        }
    }
    __syncthreads();
    if (tid < 64) {
        atomicAdd(&g_sums[mslot + 1][0][tid], s_sum[tid]);
        atomicAdd(&g_sums[mslot + 1][1][tid], s_sq[tid]);
    }
}

// final: out = g_pout + t4 @ (sc4*Wout) + bout2. MMA-based, 128 rows/CTA.
__global__ __launch_bounds__(256) void out2_kernel(float* __restrict__ out) {
    int tid = threadIdx.x, warp = tid >> 5, lane = tid & 31;
    int gid = lane >> 2, tig = lane & 3;
    size_t r = (size_t)blockIdx.x * 128 + warp * 16 + gid;
    int n = 2 * tig;

    float Co[4];
    Co[0] = (n < 3)     ? g_pout[r * 3 + n]           : 0.f;
    Co[1] = (n + 1 < 3) ? g_pout[r * 3 + n + 1]       : 0.f;
    Co[2] = (n < 3)     ? g_pout[(r + 8) * 3 + n]     : 0.f;
    Co[3] = (n + 1 < 3) ? g_pout[(r + 8) * 3 + n + 1] : 0.f;

    const uint4* tp = (const uint4*)(g_t + (size_t)4 * BATCH * HID);
    uint4 A[2][2];
    #pragma unroll
    for (int rh = 0; rh < 2; rh++) {
        size_t base = (r + rh * 8) * 8 + tig * 2;
        A[rh][0] = tp[base];
        A[rh][1] = tp[base + 1];
    }
    #pragma unroll
    for (int k4 = 0; k4 < 4; k4++) {
        uint2 of = g_OBfrag[(4 * 4 + k4) * 32 + lane];
        uint4 lo = A[0][k4 >> 1];
        uint4 hi = A[1][k4 >> 1];
        uint32_t a0 = (k4 & 1) ? lo.z : lo.x;
        uint32_t a2 = (k4 & 1) ? lo.w : lo.y;
        uint32_t a1 = (k4 & 1) ? hi.z : hi.x;
        uint32_t a3 = (k4 & 1) ? hi.w : hi.y;
        mma_f16(Co, a0, a1, a2, a3, of.x, of.y);
    }

    if (n < 3) {
        float bo = g_bout2[n];
        out[r * 3 + n]       = Co[0] + bo;
        out[(r + 8) * 3 + n] = Co[2] + bo;
    }
    if (n + 1 < 3) {
        float bo = g_bout2[n + 1];
        out[r * 3 + n + 1]       = Co[1] + bo;
        out[(r + 8) * 3 + n + 1] = Co[3] + bo;
    }
}

// ---------------- launch ----------------
extern "C" void kernel_launch(void* const* d_in, const int* in_sizes, int n_in,
                              void* d_out, int out_size) {
    const float* x    = (const float*)d_in[0];
    const float* bn0g = (const float*)d_in[1];
    const float* bn0b = (const float*)d_in[2];
    const float* W0   = (const float*)d_in[3];
    const float* b0   = (const float*)d_in[4];
    const float* g0   = (const float*)d_in[5];
    const float* be0  = (const float*)d_in[6];
    const float* Wh   = (const float*)d_in[7];
    const float* bh   = (const float*)d_in[8];
    const float* gh   = (const float*)d_in[9];
    const float* beh  = (const float*)d_in[10];
    const float* Wo   = (const float*)d_in[11];
    const float* bo   = (const float*)d_in[12];
    float* out = (float*)d_out;

    zero_kernel<<<3, 256>>>();
    xstats_kernel<<<1024, 256>>>(x);
    fin_kernel<<<1, 64>>>(0, bn0g, bn0b, 4);
    k1_kernel<<<8192, 256>>>(x, W0, b0);
    fin_kernel<<<1, 64>>>(1, g0, be0, 64);

    for (int m = 1; m <= 4; m++) {
        prep_kernel<<<m * 4 + 5, 256>>>(m, Wh + (size_t)(m - 1) * 4096, bh + (m - 1) * 64, Wo);
        switch (m) {
            case 1: midk<1, false><<<4096, 256>>>(m); break;
            case 2: midk<2, false><<<4096, 256>>>(m); break;
            case 3: midk<3, false><<<4096, 256>>>(m); break;
            case 4: midk<4, true ><<<4096, 256>>>(m); break;
        }
        fin_kernel<<<1, 64>>>(m + 1, gh + (m - 1) * 64, beh + (m - 1) * 64, 64);
    }
    prepout_kernel<<<5, 64>>>(Wo, bo);
    out2_kernel<<<8192, 256>>>(out);
}